// round 1
// baseline (speedup 1.0000x reference)
#include <cuda_runtime.h>

#define BB 32
#define NN 512
#define DINN 768
#define DOUTT 256
#define LL 512
#define NEGV -9.0e15f
#define SLOPE 0.2f

// Scratch (allocation-free per harness rules)
__device__ float g_Wh[(long)BB * NN * DOUTT];   // 16 MB
__device__ float g_s1[BB * NN];
__device__ float g_s2[BB * NN];

// ---------------------------------------------------------------------------
// Kernel 1: Wh[b,i,d] = sum_k h[b,i,k] * W[k,d] + pos_table[positions[b,i], d]
// 64x64 block tile, BK=16, 4x4 per thread, 256 threads.
// ---------------------------------------------------------------------------
__global__ __launch_bounds__(256)
void k_gemm_wh(const float* __restrict__ h, const float* __restrict__ W,
               const int* __restrict__ pos, const float* __restrict__ pt)
{
    __shared__ float As[16][65];
    __shared__ float Bs[16][65];
    const int b = blockIdx.z;
    const int rowBase = blockIdx.y * 64;
    const int colBase = blockIdx.x * 64;
    const int tid = threadIdx.x;
    const int tx = tid & 15, ty = tid >> 4;

    const float* Ab = h + (long)b * NN * DINN;
    float acc[4][4] = {};

    for (int k0 = 0; k0 < DINN; k0 += 16) {
        #pragma unroll
        for (int i = 0; i < 4; i++) {
            int idx = tid + i * 256;
            int r = idx >> 4, kk = idx & 15;
            As[kk][r] = Ab[(long)(rowBase + r) * DINN + k0 + kk];
        }
        #pragma unroll
        for (int i = 0; i < 4; i++) {
            int idx = tid + i * 256;
            int kk = idx >> 6, c = idx & 63;
            Bs[kk][c] = W[(long)(k0 + kk) * DOUTT + colBase + c];
        }
        __syncthreads();
        #pragma unroll
        for (int kk = 0; kk < 16; kk++) {
            float ra[4], rb[4];
            #pragma unroll
            for (int m = 0; m < 4; m++) ra[m] = As[kk][ty * 4 + m];
            #pragma unroll
            for (int n = 0; n < 4; n++) rb[n] = Bs[kk][tx * 4 + n];
            #pragma unroll
            for (int m = 0; m < 4; m++)
                #pragma unroll
                for (int n = 0; n < 4; n++)
                    acc[m][n] += ra[m] * rb[n];
        }
        __syncthreads();
    }

    #pragma unroll
    for (int m = 0; m < 4; m++) {
        int row = rowBase + ty * 4 + m;
        int p = pos[b * NN + row];
        const float* prow = pt + (long)p * DOUTT;
        #pragma unroll
        for (int n = 0; n < 4; n++) {
            int col = colBase + tx * 4 + n;
            g_Wh[((long)b * NN + row) * DOUTT + col] = acc[m][n] + prow[col];
        }
    }
}

// ---------------------------------------------------------------------------
// Kernel 2: s1[r] = Wh[r,:]·a1, s2[r] = Wh[r,:]·a2. One warp per row.
// ---------------------------------------------------------------------------
__global__ __launch_bounds__(256)
void k_s1s2(const float* __restrict__ a1, const float* __restrict__ a2)
{
    int row = blockIdx.x * 8 + (threadIdx.x >> 5);
    int lane = threadIdx.x & 31;
    const float* w = g_Wh + (long)row * DOUTT;
    float v1 = 0.f, v2 = 0.f;
    #pragma unroll
    for (int d = lane; d < DOUTT; d += 32) {
        float x = w[d];
        v1 += x * a1[d];
        v2 += x * a2[d];
    }
    #pragma unroll
    for (int o = 16; o; o >>= 1) {
        v1 += __shfl_down_sync(0xffffffffu, v1, o);
        v2 += __shfl_down_sync(0xffffffffu, v2, o);
    }
    if (lane == 0) { g_s1[row] = v1; g_s2[row] = v2; }
}

// ---------------------------------------------------------------------------
// Kernel 3: masked-softmax attention row. One block per (b,i), 256 threads,
// 2 neighbors each. Writes attention straight into d_out.
// ---------------------------------------------------------------------------
__global__ __launch_bounds__(256)
void k_attn(const int* __restrict__ adj, float* __restrict__ att)
{
    const int i = blockIdx.x, b = blockIdx.y;
    const long base = ((long)b * NN + i) * NN;
    const float s1v = g_s1[b * NN + i];
    const float* s2b = g_s2 + b * NN;
    const int t = threadIdx.x;

    float e[2];
    #pragma unroll
    for (int u = 0; u < 2; u++) {
        int j = t + u * 256;
        float x = s1v + s2b[j];
        x = x > 0.f ? x : SLOPE * x;
        if (adj[base + j] <= 0) x = NEGV;
        e[u] = x;
    }

    __shared__ float red[8];
    float m = fmaxf(e[0], e[1]);
    #pragma unroll
    for (int o = 16; o; o >>= 1) m = fmaxf(m, __shfl_xor_sync(0xffffffffu, m, o));
    if ((t & 31) == 0) red[t >> 5] = m;
    __syncthreads();
    float M = red[0];
    #pragma unroll
    for (int w = 1; w < 8; w++) M = fmaxf(M, red[w]);
    __syncthreads();

    float x0 = __expf(e[0] - M), x1 = __expf(e[1] - M);
    float s = x0 + x1;
    #pragma unroll
    for (int o = 16; o; o >>= 1) s += __shfl_xor_sync(0xffffffffu, s, o);
    if ((t & 31) == 0) red[t >> 5] = s;
    __syncthreads();
    float S = 0.f;
    #pragma unroll
    for (int w = 0; w < 8; w++) S += red[w];
    float inv = 1.f / S;

    att[base + t]       = x0 * inv;
    att[base + t + 256] = x1 * inv;
}

// ---------------------------------------------------------------------------
// Kernel 4: h_prime = attention @ Wh (per batch, 512x512 @ 512x256).
// Same tiling as kernel 1.
// ---------------------------------------------------------------------------
__global__ __launch_bounds__(256)
void k_gemm_hp(const float* __restrict__ att, float* __restrict__ hp)
{
    __shared__ float As[16][65];
    __shared__ float Bs[16][65];
    const int b = blockIdx.z;
    const int rowBase = blockIdx.y * 64;
    const int colBase = blockIdx.x * 64;
    const int tid = threadIdx.x;
    const int tx = tid & 15, ty = tid >> 4;

    const float* Ab = att + (long)b * NN * NN;
    const float* Bb = g_Wh + (long)b * NN * DOUTT;
    float acc[4][4] = {};

    for (int k0 = 0; k0 < NN; k0 += 16) {
        #pragma unroll
        for (int i = 0; i < 4; i++) {
            int idx = tid + i * 256;
            int r = idx >> 4, kk = idx & 15;
            As[kk][r] = Ab[(long)(rowBase + r) * NN + k0 + kk];
        }
        #pragma unroll
        for (int i = 0; i < 4; i++) {
            int idx = tid + i * 256;
            int kk = idx >> 6, c = idx & 63;
            Bs[kk][c] = Bb[(long)(k0 + kk) * DOUTT + colBase + c];
        }
        __syncthreads();
        #pragma unroll
        for (int kk = 0; kk < 16; kk++) {
            float ra[4], rb[4];
            #pragma unroll
            for (int m = 0; m < 4; m++) ra[m] = As[kk][ty * 4 + m];
            #pragma unroll
            for (int n = 0; n < 4; n++) rb[n] = Bs[kk][tx * 4 + n];
            #pragma unroll
            for (int m = 0; m < 4; m++)
                #pragma unroll
                for (int n = 0; n < 4; n++)
                    acc[m][n] += ra[m] * rb[n];
        }
        __syncthreads();
    }

    #pragma unroll
    for (int m = 0; m < 4; m++) {
        int row = rowBase + ty * 4 + m;
        #pragma unroll
        for (int n = 0; n < 4; n++) {
            int col = colBase + tx * 4 + n;
            hp[((long)b * NN + row) * DOUTT + col] = acc[m][n];
        }
    }
}

// ---------------------------------------------------------------------------
extern "C" void kernel_launch(void* const* d_in, const int* in_sizes, int n_in,
                              void* d_out, int out_size)
{
    const float* h   = (const float*)d_in[0];
    const int*   adj = (const int*)  d_in[1];
    const int*   pos = (const int*)  d_in[2];
    const float* W   = (const float*)d_in[3];
    const float* a1  = (const float*)d_in[4];
    const float* a2  = (const float*)d_in[5];
    const float* pt  = (const float*)d_in[6];

    float* out = (float*)d_out;
    float* hp  = out;                              // [B,N,DOUT]
    float* att = out + (long)BB * NN * DOUTT;      // [B,N,N]

    dim3 g1(DOUTT / 64, NN / 64, BB);   // (4, 8, 32)
    k_gemm_wh<<<g1, 256>>>(h, W, pos, pt);

    k_s1s2<<<(BB * NN) / 8, 256>>>(a1, a2);

    dim3 g3(NN, BB);                    // (512, 32)
    k_attn<<<g3, 256>>>(adj, att);

    dim3 g4(DOUTT / 64, NN / 64, BB);
    k_gemm_hp<<<g4, 256>>>(att, hp);
}

// round 3
// speedup vs baseline: 1.6286x; 1.6286x over previous
#include <cuda_runtime.h>

#define BB 32
#define NN 512
#define DINN 768
#define DOUTT 256
#define NEGV -9.0e15f
#define SLOPE 0.2f

// Scratch (allocation-free per harness rules). Referenced ONLY in device code.
__device__ float g_Wh[(long)BB * NN * DOUTT];   // 16 MB
__device__ float g_s1[BB * NN];
__device__ float g_s2[BB * NN];

// ---------------------------------------------------------------------------
// 128x128x16 double-buffered SGEMM, 256 threads, 8x8 micro-tile.
//   WH_B:   B operand is g_Wh (per-batch), Bbase ignored
//   WH_OUT: C goes to g_Wh, Cbase ignored
//   ADDPOS: add pos_table[positions] rows in epilogue
// ---------------------------------------------------------------------------
template<int KDIM, bool ADDPOS, bool WH_B, bool WH_OUT>
__global__ __launch_bounds__(256, 2)
void sgemm128(const float* __restrict__ Abase, const float* __restrict__ Bbase,
              float* __restrict__ Cbase, long aBatch,
              const int* __restrict__ pos, const float* __restrict__ pt)
{
    __shared__ float As[2][16][128];
    __shared__ float Bs[2][16][128];

    const int b = blockIdx.z;
    const float* A  = Abase + (long)b * aBatch;
    const float* Bp = WH_B ? (g_Wh + (long)b * NN * DOUTT) : Bbase;
    float*       C  = (WH_OUT ? g_Wh : Cbase) + (long)b * NN * DOUTT;

    const int rowBase = blockIdx.y * 128;
    const int colBase = blockIdx.x * 128;
    const int tid = threadIdx.x;
    const int tx = tid & 15, ty = tid >> 4;

    // global-load mapping
    const int ar0 = tid >> 2;        // A row within tile (0..63), +64 for 2nd
    const int ak0 = tid & 3;         // which float4 along K (0..3)
    const int bk0 = tid >> 5;        // B k-row (0..7), +8 for 2nd
    const int bc0 = tid & 31;        // B float4 col (0..31)

    float4 va0, va1, vb0, vb1;

    #define GLOAD(kt)                                                              \
        va0 = *(const float4*)(A  + (long)(rowBase + ar0)      * KDIM + (kt) + ak0 * 4); \
        va1 = *(const float4*)(A  + (long)(rowBase + ar0 + 64) * KDIM + (kt) + ak0 * 4); \
        vb0 = *(const float4*)(Bp + (long)((kt) + bk0)     * DOUTT + colBase + bc0 * 4); \
        vb1 = *(const float4*)(Bp + (long)((kt) + bk0 + 8) * DOUTT + colBase + bc0 * 4);

    #define SSTORE(buf)                                                            \
        As[buf][ak0 * 4 + 0][ar0]      = va0.x;                                    \
        As[buf][ak0 * 4 + 1][ar0]      = va0.y;                                    \
        As[buf][ak0 * 4 + 2][ar0]      = va0.z;                                    \
        As[buf][ak0 * 4 + 3][ar0]      = va0.w;                                    \
        As[buf][ak0 * 4 + 0][ar0 + 64] = va1.x;                                    \
        As[buf][ak0 * 4 + 1][ar0 + 64] = va1.y;                                    \
        As[buf][ak0 * 4 + 2][ar0 + 64] = va1.z;                                    \
        As[buf][ak0 * 4 + 3][ar0 + 64] = va1.w;                                    \
        *(float4*)&Bs[buf][bk0][bc0 * 4]     = vb0;                                \
        *(float4*)&Bs[buf][bk0 + 8][bc0 * 4] = vb1;

    GLOAD(0);
    SSTORE(0);
    __syncthreads();

    float acc[8][8];
    #pragma unroll
    for (int m = 0; m < 8; m++)
        #pragma unroll
        for (int n = 0; n < 8; n++) acc[m][n] = 0.f;

    const int nT = KDIM / 16;
    for (int t = 0; t < nT; ++t) {
        if (t + 1 < nT) { GLOAD((t + 1) * 16); }
        const int cur = t & 1;
        #pragma unroll
        for (int kk = 0; kk < 16; ++kk) {
            float4 a0 = *(const float4*)&As[cur][kk][ty * 4];
            float4 a1 = *(const float4*)&As[cur][kk][64 + ty * 4];
            float4 b0 = *(const float4*)&Bs[cur][kk][tx * 4];
            float4 b1 = *(const float4*)&Bs[cur][kk][64 + tx * 4];
            float av[8] = {a0.x, a0.y, a0.z, a0.w, a1.x, a1.y, a1.z, a1.w};
            float bv[8] = {b0.x, b0.y, b0.z, b0.w, b1.x, b1.y, b1.z, b1.w};
            #pragma unroll
            for (int m = 0; m < 8; m++)
                #pragma unroll
                for (int n = 0; n < 8; n++)
                    acc[m][n] += av[m] * bv[n];
        }
        if (t + 1 < nT) {
            SSTORE(cur ^ 1);
            __syncthreads();
        }
    }

    // epilogue
    #pragma unroll
    for (int half = 0; half < 2; ++half) {
        #pragma unroll
        for (int m = 0; m < 4; ++m) {
            const int row = rowBase + half * 64 + ty * 4 + m;
            const int mi = half * 4 + m;
            const float* prow = nullptr;
            if (ADDPOS) {
                int p = pos[b * NN + row];
                prow = pt + (long)p * DOUTT;
            }
            #pragma unroll
            for (int nh = 0; nh < 2; ++nh) {
                const int col = colBase + nh * 64 + tx * 4;
                float4 v;
                v.x = acc[mi][nh * 4 + 0];
                v.y = acc[mi][nh * 4 + 1];
                v.z = acc[mi][nh * 4 + 2];
                v.w = acc[mi][nh * 4 + 3];
                if (ADDPOS) {
                    v.x += prow[col];
                    v.y += prow[col + 1];
                    v.z += prow[col + 2];
                    v.w += prow[col + 3];
                }
                *(float4*)&C[(long)row * DOUTT + col] = v;
            }
        }
    }
    #undef GLOAD
    #undef SSTORE
}

// ---------------------------------------------------------------------------
// s1[r] = Wh[r,:]·a1, s2[r] = Wh[r,:]·a2. One warp per row.
// ---------------------------------------------------------------------------
__global__ __launch_bounds__(256)
void k_s1s2(const float* __restrict__ a1, const float* __restrict__ a2)
{
    int row = blockIdx.x * 8 + (threadIdx.x >> 5);
    int lane = threadIdx.x & 31;
    const float* w = g_Wh + (long)row * DOUTT;
    float v1 = 0.f, v2 = 0.f;
    #pragma unroll
    for (int d0 = 0; d0 < DOUTT; d0 += 128) {
        float4 x = *(const float4*)&w[d0 + lane * 4];
        float4 c1 = *(const float4*)&a1[d0 + lane * 4];
        float4 c2 = *(const float4*)&a2[d0 + lane * 4];
        v1 += x.x * c1.x + x.y * c1.y + x.z * c1.z + x.w * c1.w;
        v2 += x.x * c2.x + x.y * c2.y + x.z * c2.z + x.w * c2.w;
    }
    #pragma unroll
    for (int o = 16; o; o >>= 1) {
        v1 += __shfl_down_sync(0xffffffffu, v1, o);
        v2 += __shfl_down_sync(0xffffffffu, v2, o);
    }
    if (lane == 0) { g_s1[row] = v1; g_s2[row] = v2; }
}

// ---------------------------------------------------------------------------
// Masked-softmax attention row. One block of 128 threads per (b,i), 4 j each.
// ---------------------------------------------------------------------------
__global__ __launch_bounds__(128)
void k_attn(const int* __restrict__ adj, float* __restrict__ att)
{
    const int i = blockIdx.x, b = blockIdx.y;
    const long base = ((long)b * NN + i) * NN;
    const int t = threadIdx.x;
    const float s1v = g_s1[b * NN + i];

    const int4   a4 = *(const int4*)(adj + base + t * 4);
    const float4 s2 = *(const float4*)(g_s2 + b * NN + t * 4);

    float e[4];
    {
        float x;
        x = s1v + s2.x; x = x > 0.f ? x : SLOPE * x; e[0] = (a4.x > 0) ? x : NEGV;
        x = s1v + s2.y; x = x > 0.f ? x : SLOPE * x; e[1] = (a4.y > 0) ? x : NEGV;
        x = s1v + s2.z; x = x > 0.f ? x : SLOPE * x; e[2] = (a4.z > 0) ? x : NEGV;
        x = s1v + s2.w; x = x > 0.f ? x : SLOPE * x; e[3] = (a4.w > 0) ? x : NEGV;
    }

    __shared__ float red[4];
    float m = fmaxf(fmaxf(e[0], e[1]), fmaxf(e[2], e[3]));
    #pragma unroll
    for (int o = 16; o; o >>= 1) m = fmaxf(m, __shfl_xor_sync(0xffffffffu, m, o));
    if ((t & 31) == 0) red[t >> 5] = m;
    __syncthreads();
    float M = fmaxf(fmaxf(red[0], red[1]), fmaxf(red[2], red[3]));
    __syncthreads();

    float x0 = __expf(e[0] - M), x1 = __expf(e[1] - M);
    float x2 = __expf(e[2] - M), x3 = __expf(e[3] - M);
    float s = (x0 + x1) + (x2 + x3);
    #pragma unroll
    for (int o = 16; o; o >>= 1) s += __shfl_xor_sync(0xffffffffu, s, o);
    if ((t & 31) == 0) red[t >> 5] = s;
    __syncthreads();
    float inv = 1.f / (red[0] + red[1] + red[2] + red[3]);

    float4 v = make_float4(x0 * inv, x1 * inv, x2 * inv, x3 * inv);
    *(float4*)(att + base + t * 4) = v;
}

// ---------------------------------------------------------------------------
extern "C" void kernel_launch(void* const* d_in, const int* in_sizes, int n_in,
                              void* d_out, int out_size)
{
    const float* h   = (const float*)d_in[0];
    const int*   adj = (const int*)  d_in[1];
    const int*   pos = (const int*)  d_in[2];
    const float* W   = (const float*)d_in[3];
    const float* a1  = (const float*)d_in[4];
    const float* a2  = (const float*)d_in[5];
    const float* pt  = (const float*)d_in[6];

    float* out = (float*)d_out;
    float* hp  = out;                              // [B,N,DOUT]
    float* att = out + (long)BB * NN * DOUTT;      // [B,N,N]

    dim3 gg(DOUTT / 128, NN / 128, BB);            // (2, 4, 32)

    // Wh = h @ W + pos_emb   (C -> g_Wh selected in device code)
    sgemm128<DINN, true, false, true><<<gg, 256>>>(
        h, W, nullptr, (long)NN * DINN, pos, pt);

    k_s1s2<<<(BB * NN) / 8, 256>>>(a1, a2);

    dim3 g3(NN, BB);                               // (512, 32)
    k_attn<<<g3, 128>>>(adj, att);

    // h_prime = attention @ Wh   (B -> g_Wh selected in device code)
    sgemm128<NN, false, true, false><<<gg, 256>>>(
        att, nullptr, hp, (long)NN * NN, nullptr, nullptr);
}

// round 5
// speedup vs baseline: 2.2126x; 1.3586x over previous
#include <cuda_runtime.h>
#include <cuda_bf16.h>
#include <cstdint>

#define BB 32
#define NN 512
#define DINN 768
#define DOUTT 256
#define NEGV -9.0e15f
#define SLOPE 0.2f

// ---------------------------------------------------------------------------
// Scratch (allocation-free). Referenced ONLY in device code.
// ---------------------------------------------------------------------------
__device__ float         g_Wh[(long)BB * NN * DOUTT];           // 16 MB fp32 row-major
__device__ __nv_bfloat16 g_WT_hi[DOUTT * DINN];                 // W^T  [dout][din]
__device__ __nv_bfloat16 g_WT_lo[DOUTT * DINN];
__device__ __nv_bfloat16 g_WhT_hi[(long)BB * DOUTT * NN];       // Wh^T [b][dout][node]
__device__ __nv_bfloat16 g_WhT_lo[(long)BB * DOUTT * NN];
__device__ __nv_bfloat16 g_att_hi[(long)BB * NN * NN];          // att  [b][i][j]
__device__ __nv_bfloat16 g_att_lo[(long)BB * NN * NN];
__device__ float g_s1[BB * NN];
__device__ float g_s2[BB * NN];

// ---------------------------------------------------------------------------
__device__ __forceinline__ uint32_t smem_u32(const void* p) {
    uint32_t a;
    asm("{ .reg .u64 t; cvta.to.shared.u64 t, %1; cvt.u32.u64 %0, t; }" : "=r"(a) : "l"(p));
    return a;
}
__device__ __forceinline__ uint32_t pk2(float a, float b) {
    return (uint32_t)__bfloat16_as_ushort(__float2bfloat16(a)) |
           ((uint32_t)__bfloat16_as_ushort(__float2bfloat16(b)) << 16);
}
__device__ __forceinline__ float bhi(float v) {
    return __bfloat162float(__float2bfloat16(v));
}

#define LDSM_X4(R, A)                                                         \
    asm volatile("ldmatrix.sync.aligned.m8n8.x4.shared.b16 {%0,%1,%2,%3}, [%4];" \
        : "=r"((R)[0]), "=r"((R)[1]), "=r"((R)[2]), "=r"((R)[3]) : "r"(A))

#define MMA16816(D, A, B0, B1)                                                \
    asm volatile("mma.sync.aligned.m16n8k16.row.col.f32.bf16.bf16.f32 "       \
        "{%0,%1,%2,%3},{%4,%5,%6,%7},{%8,%9},{%0,%1,%2,%3};"                  \
        : "+f"((D)[0]), "+f"((D)[1]), "+f"((D)[2]), "+f"((D)[3])              \
        : "r"((A)[0]), "r"((A)[1]), "r"((A)[2]), "r"((A)[3]), "r"(B0), "r"(B1))

// smem: double-buffered operand tiles, then reused as fp32 stage [128][133]
//   buffer p (40960 B each): A_hi 0 | A_lo 10240 | B_hi 20480 | B_lo 30720
//   tile = 128 rows x 32 k bf16, row stride 80 B (pad -> ldsm conflict-free)
#define BUFB 40960
#define SMEM_TOTAL (2 * BUFB)
#define STAGE_S 133

// ---------------------------------------------------------------------------
// Pre-pass: W [din][dout] fp32 -> W^T hi/lo bf16 [dout][din]
// ---------------------------------------------------------------------------
__global__ __launch_bounds__(256)
void k_transW(const float* __restrict__ W)
{
    __shared__ float t[32][33];
    const int k0 = blockIdx.x * 32, n0 = blockIdx.y * 32;
    const int tx = threadIdx.x & 31, ty = threadIdx.x >> 5;
    #pragma unroll
    for (int j = 0; j < 4; j++) {
        int r = ty + j * 8;
        t[r][tx] = W[(long)(k0 + r) * DOUTT + n0 + tx];
    }
    __syncthreads();
    #pragma unroll
    for (int j = 0; j < 4; j++) {
        int r = ty + j * 8;
        float v = t[tx][r];
        __nv_bfloat16 h = __float2bfloat16(v);
        long o = (long)(n0 + r) * DINN + k0 + tx;
        g_WT_hi[o] = h;
        g_WT_lo[o] = __float2bfloat16(v - __bfloat162float(h));
    }
}

// ---------------------------------------------------------------------------
// Warp-MMA GEMM: D[128x128] = A[128xK] * B^T[128xK], bf16 hi/lo 3-product.
// IS1: A = h fp32 (split inline), B = W^T; epi -> g_Wh(+pos) & WhT hi/lo
// !IS1: A = att hi/lo, B = Wh^T; epi -> hp fp32
// grid (N/128=2, M/128=4, B); 256 threads; warp grid 2(M) x 4(N), 64x32/warp
// ---------------------------------------------------------------------------
template<int KDIM, bool IS1>
__global__ __launch_bounds__(256)
void mma_gemm(const float* __restrict__ Ahf, const int* __restrict__ pos,
              const float* __restrict__ pt, float* __restrict__ hp)
{
    extern __shared__ char smem[];
    const uint32_t sbase = smem_u32(smem);
    const int tid = threadIdx.x;
    const int lane = tid & 31, wid = tid >> 5;
    const int wm = wid & 1, wn = wid >> 1;
    const int b = blockIdx.z;
    const int rowBase = blockIdx.y * 128;
    const int colBase = blockIdx.x * 128;

    // per-thread global-load mapping: row = tid>>1 (0..127), half = tid&1 (k 16-elem half)
    const int lrow = tid >> 1, lhalf = tid & 1;

    const float* A1 = nullptr;
    const __nv_bfloat16 *A2h = nullptr, *A2l = nullptr;
    if (IS1) {
        A1 = Ahf + ((long)b * NN + rowBase + lrow) * DINN + lhalf * 16;
    } else {
        long ao = ((long)b * NN + rowBase + lrow) * NN + lhalf * 16;
        A2h = g_att_hi + ao;
        A2l = g_att_lo + ao;
    }
    const long bo = IS1 ? ((long)(colBase + lrow) * DINN + lhalf * 16)
                        : (((long)b * DOUTT + colBase + lrow) * NN + lhalf * 16);
    const __nv_bfloat16* Bh = (IS1 ? g_WT_hi : g_WhT_hi) + bo;
    const __nv_bfloat16* Bl = (IS1 ? g_WT_lo : g_WhT_lo) + bo;

    float acc[4][4][4];
    #pragma unroll
    for (int i = 0; i < 4; i++)
        #pragma unroll
        for (int j = 0; j < 4; j++)
            #pragma unroll
            for (int r = 0; r < 4; r++) acc[i][j][r] = 0.f;

    // staging registers for global->smem
    float4 fa[4];
    uint4 rah[2], ral[2], rbh[2], rbl[2];

    #define GLOAD(kc)                                                          \
        if (IS1) {                                                             \
            _Pragma("unroll")                                                  \
            for (int q = 0; q < 4; q++) fa[q] = *(const float4*)(A1 + (kc) + q * 4); \
        } else {                                                               \
            rah[0] = *(const uint4*)(A2h + (kc));                              \
            rah[1] = *(const uint4*)(A2h + (kc) + 8);                          \
            ral[0] = *(const uint4*)(A2l + (kc));                              \
            ral[1] = *(const uint4*)(A2l + (kc) + 8);                          \
        }                                                                      \
        rbh[0] = *(const uint4*)(Bh + (kc));                                   \
        rbh[1] = *(const uint4*)(Bh + (kc) + 8);                               \
        rbl[0] = *(const uint4*)(Bl + (kc));                                   \
        rbl[1] = *(const uint4*)(Bl + (kc) + 8);

    #define SSTORE(p)                                                          \
        {                                                                      \
            char* bufc = smem + (p) * BUFB;                                    \
            const int so = lrow * 80 + lhalf * 32;                             \
            if (IS1) {                                                         \
                _Pragma("unroll")                                              \
                for (int q = 0; q < 4; q++) {                                  \
                    uint2 hv = make_uint2(pk2(fa[q].x, fa[q].y), pk2(fa[q].z, fa[q].w)); \
                    uint2 lv = make_uint2(pk2(fa[q].x - bhi(fa[q].x), fa[q].y - bhi(fa[q].y)), \
                                          pk2(fa[q].z - bhi(fa[q].z), fa[q].w - bhi(fa[q].w))); \
                    *(uint2*)(bufc + so + q * 8)         = hv;                 \
                    *(uint2*)(bufc + 10240 + so + q * 8) = lv;                 \
                }                                                              \
            } else {                                                           \
                *(uint4*)(bufc + so)              = rah[0];                    \
                *(uint4*)(bufc + so + 16)         = rah[1];                    \
                *(uint4*)(bufc + 10240 + so)      = ral[0];                    \
                *(uint4*)(bufc + 10240 + so + 16) = ral[1];                    \
            }                                                                  \
            *(uint4*)(bufc + 20480 + so)      = rbh[0];                        \
            *(uint4*)(bufc + 20480 + so + 16) = rbh[1];                        \
            *(uint4*)(bufc + 30720 + so)      = rbl[0];                        \
            *(uint4*)(bufc + 30720 + so + 16) = rbl[1];                        \
        }

    const int arow = (wm * 64 + ((lane >> 3) & 1) * 8 + (lane & 7)) * 80;
    const int brow = (wn * 32 + ((lane >> 3) & 1) * 8 + (lane & 7)) * 80;

    #define COMPUTE(p)                                                         \
        {                                                                      \
            const uint32_t base = sbase + (p) * BUFB;                          \
            _Pragma("unroll")                                                  \
            for (int k16 = 0; k16 < 2; k16++) {                                \
                const int kb = (k16 * 16 + (lane >> 4) * 8) * 2;               \
                uint32_t a_hi[4][4], a_lo[4][4], b_hi[2][4], b_lo[2][4];       \
                _Pragma("unroll")                                              \
                for (int am = 0; am < 4; am++) {                               \
                    LDSM_X4(a_hi[am], base + arow + am * 16 * 80 + kb);        \
                    LDSM_X4(a_lo[am], base + 10240 + arow + am * 16 * 80 + kb);\
                }                                                              \
                _Pragma("unroll")                                              \
                for (int pr = 0; pr < 2; pr++) {                               \
                    LDSM_X4(b_hi[pr], base + 20480 + brow + pr * 16 * 80 + kb);\
                    LDSM_X4(b_lo[pr], base + 30720 + brow + pr * 16 * 80 + kb);\
                }                                                              \
                _Pragma("unroll")                                              \
                for (int am = 0; am < 4; am++) {                               \
                    _Pragma("unroll")                                          \
                    for (int an = 0; an < 4; an++) {                           \
                        const int pr = an >> 1, od = an & 1;                   \
                        MMA16816(acc[am][an], a_hi[am], b_hi[pr][od], b_hi[pr][od + 2]); \
                        MMA16816(acc[am][an], a_hi[am], b_lo[pr][od], b_lo[pr][od + 2]); \
                        MMA16816(acc[am][an], a_lo[am], b_hi[pr][od], b_hi[pr][od + 2]); \
                    }                                                          \
                }                                                              \
            }                                                                  \
        }

    GLOAD(0);
    SSTORE(0);
    __syncthreads();

    const int nT = KDIM / 32;
    for (int t = 0; t < nT; ++t) {
        if (t + 1 < nT) { GLOAD((t + 1) * 32); }
        COMPUTE(t & 1);
        if (t + 1 < nT) {
            SSTORE((t + 1) & 1);
            __syncthreads();
        }
    }
    __syncthreads();   // everyone done reading operand smem

    // ---- stage transposed: st[col][row], stride 133 ----
    float* st = (float*)smem;
    #pragma unroll
    for (int am = 0; am < 4; am++) {
        #pragma unroll
        for (int an = 0; an < 4; an++) {
            const int r0 = wm * 64 + am * 16 + (lane >> 2);
            const int c0 = wn * 32 + an * 8 + (lane & 3) * 2;
            st[c0 * STAGE_S + r0]           = acc[am][an][0];
            st[(c0 + 1) * STAGE_S + r0]     = acc[am][an][1];
            st[c0 * STAGE_S + r0 + 8]       = acc[am][an][2];
            st[(c0 + 1) * STAGE_S + r0 + 8] = acc[am][an][3];
        }
    }
    __syncthreads();

    if (IS1) {
        // pass1: add pos, write g_Wh fp32 (coalesced over dout), writeback stage
        #pragma unroll 4
        for (int i = 0; i < 64; i++) {
            int task = i * 8 + wid;            // 0..511
            int node = task >> 2, ch = task & 3;
            int dl = ch * 32 + lane;
            float v = st[dl * STAGE_S + node];
            int p = pos[b * NN + rowBase + node];
            v += pt[(long)p * DOUTT + colBase + dl];
            g_Wh[((long)b * NN + rowBase + node) * DOUTT + colBase + dl] = v;
            st[dl * STAGE_S + node] = v;
        }
        __syncthreads();
        // pass2: Wh^T hi/lo (coalesced over node)
        #pragma unroll 4
        for (int i = 0; i < 64; i++) {
            int task = i * 8 + wid;
            int dl = task >> 2, ch = task & 3;
            int nl = ch * 32 + lane;
            float v = st[dl * STAGE_S + nl];
            __nv_bfloat16 hv = __float2bfloat16(v);
            long o = ((long)b * DOUTT + colBase + dl) * NN + rowBase + nl;
            g_WhT_hi[o] = hv;
            g_WhT_lo[o] = __float2bfloat16(v - __bfloat162float(hv));
        }
    } else {
        #pragma unroll 4
        for (int i = 0; i < 64; i++) {
            int task = i * 8 + wid;
            int node = task >> 2, ch = task & 3;
            int dl = ch * 32 + lane;
            hp[((long)b * NN + rowBase + node) * DOUTT + colBase + dl] =
                st[dl * STAGE_S + node];
        }
    }
    #undef GLOAD
    #undef SSTORE
    #undef COMPUTE
}

// ---------------------------------------------------------------------------
// s1[r] = Wh[r,:]·a1, s2[r] = Wh[r,:]·a2. One warp per row (reads g_Wh fp32).
// ---------------------------------------------------------------------------
__global__ __launch_bounds__(256)
void k_s1s2(const float* __restrict__ a1, const float* __restrict__ a2)
{
    int row = blockIdx.x * 8 + (threadIdx.x >> 5);
    int lane = threadIdx.x & 31;
    const float* w = g_Wh + (long)row * DOUTT;
    float v1 = 0.f, v2 = 0.f;
    #pragma unroll
    for (int d0 = 0; d0 < DOUTT; d0 += 128) {
        float4 x  = *(const float4*)&w[d0 + lane * 4];
        float4 c1 = *(const float4*)&a1[d0 + lane * 4];
        float4 c2 = *(const float4*)&a2[d0 + lane * 4];
        v1 += x.x * c1.x + x.y * c1.y + x.z * c1.z + x.w * c1.w;
        v2 += x.x * c2.x + x.y * c2.y + x.z * c2.z + x.w * c2.w;
    }
    #pragma unroll
    for (int o = 16; o; o >>= 1) {
        v1 += __shfl_down_sync(0xffffffffu, v1, o);
        v2 += __shfl_down_sync(0xffffffffu, v2, o);
    }
    if (lane == 0) { g_s1[row] = v1; g_s2[row] = v2; }
}

// ---------------------------------------------------------------------------
// Masked-softmax attention row: fp32 att to d_out + hi/lo bf16 scratch.
// ---------------------------------------------------------------------------
__global__ __launch_bounds__(128)
void k_attn(const int* __restrict__ adj, float* __restrict__ att)
{
    const int i = blockIdx.x, b = blockIdx.y;
    const long base = ((long)b * NN + i) * NN;
    const int t = threadIdx.x;
    const float s1v = g_s1[b * NN + i];

    const int4   a4 = *(const int4*)(adj + base + t * 4);
    const float4 s2 = *(const float4*)(g_s2 + b * NN + t * 4);

    float e[4];
    {
        float x;
        x = s1v + s2.x; x = x > 0.f ? x : SLOPE * x; e[0] = (a4.x > 0) ? x : NEGV;
        x = s1v + s2.y; x = x > 0.f ? x : SLOPE * x; e[1] = (a4.y > 0) ? x : NEGV;
        x = s1v + s2.z; x = x > 0.f ? x : SLOPE * x; e[2] = (a4.z > 0) ? x : NEGV;
        x = s1v + s2.w; x = x > 0.f ? x : SLOPE * x; e[3] = (a4.w > 0) ? x : NEGV;
    }

    __shared__ float red[4];
    float m = fmaxf(fmaxf(e[0], e[1]), fmaxf(e[2], e[3]));
    #pragma unroll
    for (int o = 16; o; o >>= 1) m = fmaxf(m, __shfl_xor_sync(0xffffffffu, m, o));
    if ((t & 31) == 0) red[t >> 5] = m;
    __syncthreads();
    float M = fmaxf(fmaxf(red[0], red[1]), fmaxf(red[2], red[3]));
    __syncthreads();

    float x0 = __expf(e[0] - M), x1 = __expf(e[1] - M);
    float x2 = __expf(e[2] - M), x3 = __expf(e[3] - M);
    float s = (x0 + x1) + (x2 + x3);
    #pragma unroll
    for (int o = 16; o; o >>= 1) s += __shfl_xor_sync(0xffffffffu, s, o);
    if ((t & 31) == 0) red[t >> 5] = s;
    __syncthreads();
    float inv = 1.f / (red[0] + red[1] + red[2] + red[3]);

    float v0 = x0 * inv, v1 = x1 * inv, v2 = x2 * inv, v3 = x3 * inv;
    *(float4*)(att + base + t * 4) = make_float4(v0, v1, v2, v3);

    uint32_t h0 = pk2(v0, v1), h1 = pk2(v2, v3);
    uint32_t l0 = pk2(v0 - bhi(v0), v1 - bhi(v1));
    uint32_t l1 = pk2(v2 - bhi(v2), v3 - bhi(v3));
    *(uint2*)(g_att_hi + base + t * 4) = make_uint2(h0, h1);
    *(uint2*)(g_att_lo + base + t * 4) = make_uint2(l0, l1);
}

// ---------------------------------------------------------------------------
extern "C" void kernel_launch(void* const* d_in, const int* in_sizes, int n_in,
                              void* d_out, int out_size)
{
    const float* h   = (const float*)d_in[0];
    const int*   adj = (const int*)  d_in[1];
    const int*   pos = (const int*)  d_in[2];
    const float* W   = (const float*)d_in[3];
    const float* a1  = (const float*)d_in[4];
    const float* a2  = (const float*)d_in[5];
    const float* pt  = (const float*)d_in[6];

    float* out = (float*)d_out;
    float* hp  = out;                              // [B,N,DOUT]
    float* att = out + (long)BB * NN * DOUTT;      // [B,N,N]

    static int smem_set = 0;
    if (!smem_set) {
        cudaFuncSetAttribute(mma_gemm<DINN, true>,
                             cudaFuncAttributeMaxDynamicSharedMemorySize, SMEM_TOTAL);
        cudaFuncSetAttribute(mma_gemm<NN, false>,
                             cudaFuncAttributeMaxDynamicSharedMemorySize, SMEM_TOTAL);
        smem_set = 1;
    }

    dim3 gT(DINN / 32, DOUTT / 32);                // (24, 8)
    k_transW<<<gT, 256>>>(W);

    dim3 gG(DOUTT / 128, NN / 128, BB);            // (2, 4, 32)
    mma_gemm<DINN, true><<<gG, 256, SMEM_TOTAL>>>(h, pos, pt, nullptr);

    k_s1s2<<<(BB * NN) / 8, 256>>>(a1, a2);

    dim3 g3(NN, BB);                               // (512, 32)
    k_attn<<<g3, 128>>>(adj, att);

    mma_gemm<NN, false><<<gG, 256, SMEM_TOTAL>>>(nullptr, nullptr, nullptr, hp);
}

// round 6
// speedup vs baseline: 2.4307x; 1.0986x over previous
#include <cuda_runtime.h>
#include <cuda_bf16.h>
#include <cstdint>

#define BB 32
#define NN 512
#define DINN 768
#define DOUTT 256
#define NEGV -9.0e15f
#define SLOPE 0.2f

// ---------------------------------------------------------------------------
// Scratch (allocation-free). Referenced ONLY in device code.
// ---------------------------------------------------------------------------
__device__ __nv_bfloat16 g_WT_hi[DOUTT * DINN];                 // W^T  [dout][din]
__device__ __nv_bfloat16 g_WT_lo[DOUTT * DINN];
__device__ __nv_bfloat16 g_WhT_hi[(long)BB * DOUTT * NN];       // Wh^T [b][dout][node]
__device__ __nv_bfloat16 g_WhT_lo[(long)BB * DOUTT * NN];
__device__ __nv_bfloat16 g_att_hi[(long)BB * NN * NN];          // att  [b][i][j]
__device__ __nv_bfloat16 g_att_lo[(long)BB * NN * NN];
__device__ float g_s1[BB * NN];
__device__ float g_s2[BB * NN];

// ---------------------------------------------------------------------------
__device__ __forceinline__ uint32_t smem_u32(const void* p) {
    uint32_t a;
    asm("{ .reg .u64 t; cvta.to.shared.u64 t, %1; cvt.u32.u64 %0, t; }" : "=r"(a) : "l"(p));
    return a;
}
__device__ __forceinline__ uint32_t pk2(float a, float b) {
    return (uint32_t)__bfloat16_as_ushort(__float2bfloat16(a)) |
           ((uint32_t)__bfloat16_as_ushort(__float2bfloat16(b)) << 16);
}
__device__ __forceinline__ float bhi(float v) {
    return __bfloat162float(__float2bfloat16(v));
}
__device__ __forceinline__ void cpa16(uint32_t s, const void* g) {
    asm volatile("cp.async.cg.shared.global [%0], [%1], 16;" :: "r"(s), "l"(g));
}

#define LDSM_X4(R, A)                                                         \
    asm volatile("ldmatrix.sync.aligned.m8n8.x4.shared.b16 {%0,%1,%2,%3}, [%4];" \
        : "=r"((R)[0]), "=r"((R)[1]), "=r"((R)[2]), "=r"((R)[3]) : "r"(A))

#define MMA16816(D, A, B0, B1)                                                \
    asm volatile("mma.sync.aligned.m16n8k16.row.col.f32.bf16.bf16.f32 "       \
        "{%0,%1,%2,%3},{%4,%5,%6,%7},{%8,%9},{%0,%1,%2,%3};"                  \
        : "+f"((D)[0]), "+f"((D)[1]), "+f"((D)[2]), "+f"((D)[3])              \
        : "r"((A)[0]), "r"((A)[1]), "r"((A)[2]), "r"((A)[3]), "r"(B0), "r"(B1))

// operand smem (per buffer): A_hi | A_lo | B_hi | B_lo ; rows stride 80 B
#define AHI 0
#define ALO 10240
#define BHI 20480
#define BLO 40960
#define BUFB 61440
#define STG1 132      // GEMM1 stage: st[col*132 + row], 256x132 fp32
#define STG2 264      // GEMM2 stage: st[row*264 + col], 128x264 fp32
#define SMEM_TOTAL 135680   // max(2*BUFB=122880, stage 135168) + 512 pos

// ---------------------------------------------------------------------------
// Pre-pass: W [din][dout] fp32 -> W^T hi/lo bf16 [dout][din]
// ---------------------------------------------------------------------------
__global__ __launch_bounds__(256)
void k_transW(const float* __restrict__ W)
{
    __shared__ float t[32][33];
    const int k0 = blockIdx.x * 32, n0 = blockIdx.y * 32;
    const int tx = threadIdx.x & 31, ty = threadIdx.x >> 5;
    #pragma unroll
    for (int j = 0; j < 4; j++) {
        int r = ty + j * 8;
        t[r][tx] = W[(long)(k0 + r) * DOUTT + n0 + tx];
    }
    __syncthreads();
    #pragma unroll
    for (int j = 0; j < 4; j++) {
        int r = ty + j * 8;
        float v = t[tx][r];
        __nv_bfloat16 h = __float2bfloat16(v);
        long o = (long)(n0 + r) * DINN + k0 + tx;
        g_WT_hi[o] = h;
        g_WT_lo[o] = __float2bfloat16(v - __bfloat162float(h));
    }
}

// ---------------------------------------------------------------------------
// Warp-MMA GEMM: D[128 x 256] = A[128xK] * B^T[256xK], bf16 hi/lo 3-product.
// IS1: A = h fp32 (split inline), B = W^T; epi -> WhT hi/lo + s1/s2 (fused)
// !IS1: A = att hi/lo, B = Wh^T; epi -> hp fp32
// grid (NN/128=4, BB); 256 threads; warps 2(M)x4(N), 64x64 per warp
// ---------------------------------------------------------------------------
template<int KDIM, bool IS1>
__global__ __launch_bounds__(256, 1)
void mma_gemm(const float* __restrict__ Ahf, const int* __restrict__ pos,
              const float* __restrict__ pt, const float* __restrict__ a1v,
              const float* __restrict__ a2v, float* __restrict__ hp)
{
    extern __shared__ char smem[];
    const uint32_t sbase = smem_u32(smem);
    const int tid = threadIdx.x;
    const int lane = tid & 31, wid = tid >> 5;
    const int wm = wid & 1, wn = wid >> 1;
    const int b = blockIdx.y;
    const int rowBase = blockIdx.x * 128;

    // A fp32 register path (IS1 only)
    const int lrow = tid >> 1, lhalf = tid & 1;
    const float* A1 = IS1 ? (Ahf + ((long)b * NN + rowBase + lrow) * DINN + lhalf * 16)
                          : nullptr;
    float4 fa[4];

    float acc[4][8][4];
    #pragma unroll
    for (int i = 0; i < 4; i++)
        #pragma unroll
        for (int j = 0; j < 8; j++)
            #pragma unroll
            for (int r = 0; r < 4; r++) acc[i][j][r] = 0.f;

    auto BISSUE = [&](int kc, int p) {
        const uint32_t sb2 = sbase + p * BUFB;
        #pragma unroll
        for (int i = 0; i < 4; i++) {                 // B: 256 rows x 64B
            int idx = i * 256 + tid;
            int r = idx >> 2, c4 = idx & 3;
            long go = IS1 ? ((long)r * DINN + kc + c4 * 8)
                          : (((long)b * DOUTT + r) * NN + kc + c4 * 8);
            uint32_t so = r * 80 + c4 * 16;
            cpa16(sb2 + BHI + so, (IS1 ? g_WT_hi : g_WhT_hi) + go);
            cpa16(sb2 + BLO + so, (IS1 ? g_WT_lo : g_WhT_lo) + go);
        }
        if (!IS1) {
            #pragma unroll
            for (int i = 0; i < 2; i++) {             // A: 128 rows x 64B
                int idx = i * 256 + tid;
                int r = idx >> 2, c4 = idx & 3;
                long go = ((long)b * NN + rowBase + r) * NN + kc + c4 * 8;
                uint32_t so = r * 80 + c4 * 16;
                cpa16(sb2 + AHI + so, g_att_hi + go);
                cpa16(sb2 + ALO + so, g_att_lo + go);
            }
        }
        asm volatile("cp.async.commit_group;" ::: "memory");
    };
    auto ALOADR = [&](int kc) {
        if (IS1) {
            #pragma unroll
            for (int q = 0; q < 4; q++) fa[q] = *(const float4*)(A1 + kc + q * 4);
        }
    };
    auto ASTORE = [&](int p) {
        if (IS1) {
            char* bufc = smem + p * BUFB;
            const int so = lrow * 80 + lhalf * 32;
            #pragma unroll
            for (int q = 0; q < 4; q++) {
                uint2 hv = make_uint2(pk2(fa[q].x, fa[q].y), pk2(fa[q].z, fa[q].w));
                uint2 lv = make_uint2(pk2(fa[q].x - bhi(fa[q].x), fa[q].y - bhi(fa[q].y)),
                                      pk2(fa[q].z - bhi(fa[q].z), fa[q].w - bhi(fa[q].w)));
                *(uint2*)(bufc + AHI + so + q * 8) = hv;
                *(uint2*)(bufc + ALO + so + q * 8) = lv;
            }
        }
    };

    const int arow = (wm * 64 + ((lane >> 3) & 1) * 8 + (lane & 7)) * 80;
    const int brow = (wn * 64 + ((lane >> 3) & 1) * 8 + (lane & 7)) * 80;

    auto COMPUTE = [&](int p) {
        const uint32_t base = sbase + p * BUFB;
        #pragma unroll
        for (int k16 = 0; k16 < 2; k16++) {
            const int kb = (k16 * 16 + (lane >> 4) * 8) * 2;
            uint32_t a_hi[4][4], a_lo[4][4];
            #pragma unroll
            for (int am = 0; am < 4; am++) {
                LDSM_X4(a_hi[am], base + AHI + arow + am * 16 * 80 + kb);
                LDSM_X4(a_lo[am], base + ALO + arow + am * 16 * 80 + kb);
            }
            #pragma unroll
            for (int pr = 0; pr < 4; pr++) {
                uint32_t b_hi[4], b_lo[4];
                LDSM_X4(b_hi, base + BHI + brow + pr * 16 * 80 + kb);
                LDSM_X4(b_lo, base + BLO + brow + pr * 16 * 80 + kb);
                #pragma unroll
                for (int od = 0; od < 2; od++) {
                    const int an = pr * 2 + od;
                    #pragma unroll
                    for (int am = 0; am < 4; am++) {
                        MMA16816(acc[am][an], a_hi[am], b_hi[od], b_hi[od + 2]);
                        MMA16816(acc[am][an], a_hi[am], b_lo[od], b_lo[od + 2]);
                        MMA16816(acc[am][an], a_lo[am], b_hi[od], b_hi[od + 2]);
                    }
                }
            }
        }
    };

    // ---- pipeline ----
    ALOADR(0);
    BISSUE(0, 0);
    ASTORE(0);

    const int nT = KDIM / 32;
    for (int t = 0; t < nT; ++t) {
        if (t + 1 < nT) {
            ALOADR((t + 1) * 32);
            BISSUE((t + 1) * 32, (t + 1) & 1);
            asm volatile("cp.async.wait_group 1;" ::: "memory");
        } else {
            asm volatile("cp.async.wait_group 0;" ::: "memory");
        }
        __syncthreads();
        COMPUTE(t & 1);
        __syncthreads();
        if (t + 1 < nT) ASTORE((t + 1) & 1);
    }

    // ---- epilogue (operand smem now reused as fp32 stage) ----
    float* st = (float*)smem;
    if (IS1) {
        int* pos_s = (int*)(smem + 135168);
        // stage transposed: st[col*STG1 + row]
        #pragma unroll
        for (int am = 0; am < 4; am++)
            #pragma unroll
            for (int an = 0; an < 8; an++) {
                const int r0 = wm * 64 + am * 16 + (lane >> 2);
                const int c0 = wn * 64 + an * 8 + (lane & 3) * 2;
                st[c0 * STG1 + r0]           = acc[am][an][0];
                st[(c0 + 1) * STG1 + r0]     = acc[am][an][1];
                st[c0 * STG1 + r0 + 8]       = acc[am][an][2];
                st[(c0 + 1) * STG1 + r0 + 8] = acc[am][an][3];
            }
        if (tid < 128) pos_s[tid] = pos[b * NN + rowBase + tid];
        __syncthreads();
        // pass A: add pos-emb, write WhT hi/lo, update stage
        #pragma unroll 2
        for (int i = 0; i < 128; i++) {
            int idx = i * 256 + tid;
            int dl = idx >> 7, nl = idx & 127;
            float v = st[dl * STG1 + nl] + __ldg(pt + (long)pos_s[nl] * DOUTT + dl);
            st[dl * STG1 + nl] = v;
            __nv_bfloat16 hv = __float2bfloat16(v);
            long o = ((long)b * DOUTT + dl) * NN + rowBase + nl;
            g_WhT_hi[o] = hv;
            g_WhT_lo[o] = __float2bfloat16(v - __bfloat162float(hv));
        }
        __syncthreads();
        // pass B: fused s1/s2 (full DOUT rows in this CTA)
        {
            const int node = tid >> 1, half = tid & 1;
            float v1 = 0.f, v2 = 0.f;
            #pragma unroll 4
            for (int c = 0; c < 128; c++) {
                int dl = half * 128 + c;
                float v = st[dl * STG1 + node];
                v1 += v * __ldg(a1v + dl);
                v2 += v * __ldg(a2v + dl);
            }
            v1 += __shfl_down_sync(0xffffffffu, v1, 1);
            v2 += __shfl_down_sync(0xffffffffu, v2, 1);
            if (half == 0) {
                g_s1[b * NN + rowBase + node] = v1;
                g_s2[b * NN + rowBase + node] = v2;
            }
        }
    } else {
        // stage row-major: st[row*STG2 + col]
        #pragma unroll
        for (int am = 0; am < 4; am++)
            #pragma unroll
            for (int an = 0; an < 8; an++) {
                const int r0 = wm * 64 + am * 16 + (lane >> 2);
                const int c0 = wn * 64 + an * 8 + (lane & 3) * 2;
                st[r0 * STG2 + c0]           = acc[am][an][0];
                st[r0 * STG2 + c0 + 1]       = acc[am][an][1];
                st[(r0 + 8) * STG2 + c0]     = acc[am][an][2];
                st[(r0 + 8) * STG2 + c0 + 1] = acc[am][an][3];
            }
        __syncthreads();
        #pragma unroll 4
        for (int i = 0; i < 32; i++) {
            int fid = i * 256 + tid;
            int r = fid >> 6, c4 = fid & 63;
            float4 v = *(const float4*)&st[r * STG2 + c4 * 4];
            *(float4*)&hp[((long)b * NN + rowBase + r) * DOUTT + c4 * 4] = v;
        }
    }
}

// ---------------------------------------------------------------------------
// Masked-softmax attention row: fp32 att to d_out + hi/lo bf16 scratch.
// ---------------------------------------------------------------------------
__global__ __launch_bounds__(128)
void k_attn(const int* __restrict__ adj, float* __restrict__ att)
{
    const int i = blockIdx.x, b = blockIdx.y;
    const long base = ((long)b * NN + i) * NN;
    const int t = threadIdx.x;
    const float s1v = g_s1[b * NN + i];

    const int4   a4 = *(const int4*)(adj + base + t * 4);
    const float4 s2 = *(const float4*)(g_s2 + b * NN + t * 4);

    float e[4];
    {
        float x;
        x = s1v + s2.x; x = x > 0.f ? x : SLOPE * x; e[0] = (a4.x > 0) ? x : NEGV;
        x = s1v + s2.y; x = x > 0.f ? x : SLOPE * x; e[1] = (a4.y > 0) ? x : NEGV;
        x = s1v + s2.z; x = x > 0.f ? x : SLOPE * x; e[2] = (a4.z > 0) ? x : NEGV;
        x = s1v + s2.w; x = x > 0.f ? x : SLOPE * x; e[3] = (a4.w > 0) ? x : NEGV;
    }

    __shared__ float red[4];
    float m = fmaxf(fmaxf(e[0], e[1]), fmaxf(e[2], e[3]));
    #pragma unroll
    for (int o = 16; o; o >>= 1) m = fmaxf(m, __shfl_xor_sync(0xffffffffu, m, o));
    if ((t & 31) == 0) red[t >> 5] = m;
    __syncthreads();
    float M = fmaxf(fmaxf(red[0], red[1]), fmaxf(red[2], red[3]));
    __syncthreads();

    float x0 = __expf(e[0] - M), x1 = __expf(e[1] - M);
    float x2 = __expf(e[2] - M), x3 = __expf(e[3] - M);
    float s = (x0 + x1) + (x2 + x3);
    #pragma unroll
    for (int o = 16; o; o >>= 1) s += __shfl_xor_sync(0xffffffffu, s, o);
    if ((t & 31) == 0) red[t >> 5] = s;
    __syncthreads();
    float inv = 1.f / (red[0] + red[1] + red[2] + red[3]);

    float v0 = x0 * inv, v1 = x1 * inv, v2 = x2 * inv, v3 = x3 * inv;
    *(float4*)(att + base + t * 4) = make_float4(v0, v1, v2, v3);

    uint32_t h0 = pk2(v0, v1), h1 = pk2(v2, v3);
    uint32_t l0 = pk2(v0 - bhi(v0), v1 - bhi(v1));
    uint32_t l1 = pk2(v2 - bhi(v2), v3 - bhi(v3));
    *(uint2*)(g_att_hi + base + t * 4) = make_uint2(h0, h1);
    *(uint2*)(g_att_lo + base + t * 4) = make_uint2(l0, l1);
}

// ---------------------------------------------------------------------------
extern "C" void kernel_launch(void* const* d_in, const int* in_sizes, int n_in,
                              void* d_out, int out_size)
{
    const float* h   = (const float*)d_in[0];
    const int*   adj = (const int*)  d_in[1];
    const int*   pos = (const int*)  d_in[2];
    const float* W   = (const float*)d_in[3];
    const float* a1  = (const float*)d_in[4];
    const float* a2  = (const float*)d_in[5];
    const float* pt  = (const float*)d_in[6];

    float* out = (float*)d_out;
    float* hp  = out;                              // [B,N,DOUT]
    float* att = out + (long)BB * NN * DOUTT;      // [B,N,N]

    static int smem_set = 0;
    if (!smem_set) {
        cudaFuncSetAttribute(mma_gemm<DINN, true>,
                             cudaFuncAttributeMaxDynamicSharedMemorySize, SMEM_TOTAL);
        cudaFuncSetAttribute(mma_gemm<NN, false>,
                             cudaFuncAttributeMaxDynamicSharedMemorySize, SMEM_TOTAL);
        smem_set = 1;
    }

    dim3 gT(DINN / 32, DOUTT / 32);                // (24, 8)
    k_transW<<<gT, 256>>>(W);

    dim3 gG(NN / 128, BB);                         // (4, 32) = 128 CTAs
    mma_gemm<DINN, true><<<gG, 256, SMEM_TOTAL>>>(h, pos, pt, a1, a2, nullptr);

    dim3 g3(NN, BB);                               // (512, 32)
    k_attn<<<g3, 128>>>(adj, att);

    mma_gemm<NN, false><<<gG, 256, SMEM_TOTAL>>>(nullptr, nullptr, nullptr,
                                                 nullptr, nullptr, hp);
}